// round 11
// baseline (speedup 1.0000x reference)
#include <cuda_runtime.h>
#include <cstdint>

#define N_NODES 100000
#define N_EDGES 1600000
#define NF 100
#define NH 32

typedef unsigned long long u64;

// ---------------- device scratch (no allocations allowed) ----------------
// g_deg and g_cursor are zero at module load; k_agg2 re-zeroes them at the end
// of every call so each graph replay starts from the same state.
__device__ int      g_cursor;
__device__ int      g_deg    [N_NODES];
__device__ int      g_off    [N_NODES];
__device__ int      g_fillpos[N_NODES];
__device__ float    g_dinv   [N_NODES];
__device__ unsigned g_mask   [N_NODES];    // 32-bit dropout keep-mask per node
__device__ int      g_csr    [N_EDGES];    // src per CSR slot (grouped by dst)
__device__ float    g_h      [N_NODES * NH];  // h' = (x @ W1) * dinv[row]
__device__ float    g_g      [N_NODES * 2];   // g' = (dropout(relu(.+b1)) @ W2) * dinv[row]

// ---------------- helpers ----------------
// Block-local int64-vs-int32 detection: for int64 ids < 2^31 every odd 32-bit
// word of the src half is zero; for int32 those words are random node ids.
__device__ __forceinline__ int detect_is64(const unsigned* ei) {
    int any = (ei[2 * threadIdx.x + 1] != 0u) ? 1 : 0;
    return __syncthreads_or(any) ? 0 : 1;
}

// JAX threefry2x32, key = (0, 42)  [jax.random.key(42)], 20 rounds
__device__ __forceinline__ uint2 threefry_0_42(unsigned x0, unsigned x1) {
    const unsigned ks0 = 0u, ks1 = 42u, ks2 = 0x1BD11BDAu ^ 42u;
    x0 += ks0; x1 += ks1;
#define TFR(r) { x0 += x1; x1 = ((x1 << (r)) | (x1 >> (32 - (r)))) ^ x0; }
    TFR(13) TFR(15) TFR(26) TFR(6)
    x0 += ks1; x1 += ks2 + 1u;
    TFR(17) TFR(29) TFR(16) TFR(24)
    x0 += ks2; x1 += ks0 + 2u;
    TFR(13) TFR(15) TFR(26) TFR(6)
    x0 += ks0; x1 += ks1 + 3u;
    TFR(17) TFR(29) TFR(16) TFR(24)
    x0 += ks1; x1 += ks2 + 4u;
    TFR(13) TFR(15) TFR(26) TFR(6)
    x0 += ks2; x1 += ks0 + 5u;
#undef TFR
    return make_uint2(x0, x1);
}

// Partitionable threefry: counter (0, idx), bits = out0 ^ out1.
// keep iff (bits >> 9) < 6710887  (u < 0.8f)
__device__ __forceinline__ int keep_bit(unsigned idx) {
    uint2 o = threefry_0_42(0u, idx);
    return (((o.x ^ o.y) >> 9) < 6710887u) ? 1 : 0;
}

// ---------------- kernels ----------------

// Per edge: count in-degree. 4 edges per thread (vector loads, ILP-4 atomics).
__global__ __launch_bounds__(256) void k_deg(const unsigned* ei) {
    int is64 = detect_is64(ei);
    int e0 = (blockIdx.x * 256 + threadIdx.x) * 4;
    if (e0 >= N_EDGES) return;
    int d0, d1, d2, d3;
    if (is64) {
        const longlong2* p = (const longlong2*)((const long long*)ei + N_EDGES + e0);
        longlong2 a = __ldg(p), b = __ldg(p + 1);
        d0 = (int)a.x; d1 = (int)a.y; d2 = (int)b.x; d3 = (int)b.y;
    } else {
        int4 v = __ldg((const int4*)((const int*)ei + N_EDGES + e0));
        d0 = v.x; d1 = v.y; d2 = v.z; d3 = v.w;
    }
    atomicAdd(&g_deg[d0], 1);
    atomicAdd(&g_deg[d1], 1);
    atomicAdd(&g_deg[d2], 1);
    atomicAdd(&g_deg[d3], 1);
}

// Prologue: per-block scan of deg -> CSR offsets (order-free via global cursor),
// dinv = rsqrt(deg+1), fillpos = off. Body: h' = (x @ W1) * dinv.
// Block: 256 threads = 256 rows x 32 cols. Thread: 4 rows x 8 cols.
__global__ __launch_bounds__(256) void k_gemm1(const float* __restrict__ x,
                                               const float* __restrict__ W1) {
    __shared__ float Ws[NF * NH];      // 100x32
    __shared__ float xs[20 * 264];     // k-chunk of x, transposed, padded
    __shared__ int   s_scan[256];
    __shared__ int   s_base;
    const int tid  = threadIdx.x;
    const int row0 = blockIdx.x * 256;
    const int rg = tid >> 2;           // 0..63 -> rows rg*4..rg*4+3
    const int cg = tid & 3;            // 0..3  -> cols cg*8..cg*8+7

    // ---- offsets + dinv prologue ----
    {
        int gr = row0 + tid;
        int mydeg = (gr < N_NODES) ? g_deg[gr] : 0;
        if (gr < N_NODES) g_dinv[gr] = rsqrtf((float)(mydeg + 1));
        s_scan[tid] = mydeg;
        __syncthreads();
#pragma unroll
        for (int off = 1; off < 256; off <<= 1) {
            int v = (tid >= off) ? s_scan[tid - off] : 0;
            __syncthreads();
            s_scan[tid] += v;
            __syncthreads();
        }
        if (tid == 255) s_base = atomicAdd(&g_cursor, s_scan[255]);
        __syncthreads();
        if (gr < N_NODES) {
            int my_off = s_base + s_scan[tid] - mydeg;
            g_off[gr] = my_off;
            g_fillpos[gr] = my_off;
        }
    }

    for (int i = tid; i < NF * NH; i += 256) Ws[i] = W1[i];

    u64 acc[4][4];
#pragma unroll
    for (int i = 0; i < 4; i++)
#pragma unroll
        for (int j = 0; j < 4; j++) acc[i][j] = 0ull;

    for (int kc = 0; kc < 5; kc++) {
        __syncthreads();
        {
            int gr = row0 + tid;
            if (gr >= N_NODES) gr = N_NODES - 1;
            const float4* xp = (const float4*)(x + (size_t)gr * NF + kc * 20);
#pragma unroll
            for (int q = 0; q < 5; q++) {
                float4 v = __ldg(xp + q);
                xs[(q * 4 + 0) * 264 + tid] = v.x;
                xs[(q * 4 + 1) * 264 + tid] = v.y;
                xs[(q * 4 + 2) * 264 + tid] = v.z;
                xs[(q * 4 + 3) * 264 + tid] = v.w;
            }
        }
        __syncthreads();
#pragma unroll
        for (int kk = 0; kk < 20; kk++) {
            float4 xv = *(const float4*)&xs[kk * 264 + rg * 4];
            const u64* wp = (const u64*)&Ws[(kc * 20 + kk) * NH + cg * 8];
            u64 w0 = wp[0], w1 = wp[1], w2 = wp[2], w3 = wp[3];
            u64 xd0, xd1, xd2, xd3;
            asm("mov.b64 %0,{%1,%1};" : "=l"(xd0) : "r"(__float_as_uint(xv.x)));
            asm("mov.b64 %0,{%1,%1};" : "=l"(xd1) : "r"(__float_as_uint(xv.y)));
            asm("mov.b64 %0,{%1,%1};" : "=l"(xd2) : "r"(__float_as_uint(xv.z)));
            asm("mov.b64 %0,{%1,%1};" : "=l"(xd3) : "r"(__float_as_uint(xv.w)));
#define FMA2(a, b, c) asm("fma.rn.f32x2 %0,%1,%2,%0;" : "+l"(a) : "l"(b), "l"(c))
            FMA2(acc[0][0], xd0, w0); FMA2(acc[0][1], xd0, w1);
            FMA2(acc[0][2], xd0, w2); FMA2(acc[0][3], xd0, w3);
            FMA2(acc[1][0], xd1, w0); FMA2(acc[1][1], xd1, w1);
            FMA2(acc[1][2], xd1, w2); FMA2(acc[1][3], xd1, w3);
            FMA2(acc[2][0], xd2, w0); FMA2(acc[2][1], xd2, w1);
            FMA2(acc[2][2], xd2, w2); FMA2(acc[2][3], xd2, w3);
            FMA2(acc[3][0], xd3, w0); FMA2(acc[3][1], xd3, w1);
            FMA2(acc[3][2], xd3, w2); FMA2(acc[3][3], xd3, w3);
#undef FMA2
        }
    }

    // h' = h * dinv[row]  (dinv for in-block rows written in prologue)
#pragma unroll
    for (int ri = 0; ri < 4; ri++) {
        int gr = row0 + rg * 4 + ri;
        if (gr < N_NODES) {
            float di = g_dinv[gr];
            float2 p0 = *(float2*)&acc[ri][0];
            float2 p1 = *(float2*)&acc[ri][1];
            float2 p2 = *(float2*)&acc[ri][2];
            float2 p3 = *(float2*)&acc[ri][3];
            float* hp = g_h + (size_t)gr * NH + cg * 8;
            *(float4*)(hp)     = make_float4(p0.x * di, p0.y * di, p1.x * di, p1.y * di);
            *(float4*)(hp + 4) = make_float4(p2.x * di, p2.y * di, p3.x * di, p3.y * di);
        }
    }
}

// Scatter src into CSR slots (4 edges/thread, atomic cursor per dst) AND
// compute dropout masks: each warp covers 8 nodes via 8 ballot rounds (threefry
// ALU hides under the memory stalls). Grid = N_EDGES/4 threads.
__global__ __launch_bounds__(256) void k_fill(const unsigned* ei) {
    int is64 = detect_is64(ei);
    int t = blockIdx.x * 256 + threadIdx.x;
    int lane = threadIdx.x & 31;

    // dropout masks: warp w -> nodes 8w .. 8w+7
    int w = t >> 5;
    int nbase = w * 8;
    unsigned mymask = 0;
#pragma unroll
    for (int j = 0; j < 8; j++) {
        int n = nbase + j;
        unsigned m = __ballot_sync(0xffffffffu,
                                   (n < N_NODES) && keep_bit((unsigned)(n * 32 + lane)));
        if (lane == j) mymask = m;
    }
    if (lane < 8 && nbase + lane < N_NODES) g_mask[nbase + lane] = mymask;

    // CSR fill: 4 edges per thread
    int e0 = t * 4;
    if (e0 >= N_EDGES) return;
    int s0, s1, s2, s3, d0, d1, d2, d3;
    if (is64) {
        const longlong2* ps = (const longlong2*)((const long long*)ei + e0);
        const longlong2* pd = (const longlong2*)((const long long*)ei + N_EDGES + e0);
        longlong2 sa = __ldg(ps), sb = __ldg(ps + 1);
        longlong2 da = __ldg(pd), db = __ldg(pd + 1);
        s0 = (int)sa.x; s1 = (int)sa.y; s2 = (int)sb.x; s3 = (int)sb.y;
        d0 = (int)da.x; d1 = (int)da.y; d2 = (int)db.x; d3 = (int)db.y;
    } else {
        int4 sv = __ldg((const int4*)((const int*)ei + e0));
        int4 dv = __ldg((const int4*)((const int*)ei + N_EDGES + e0));
        s0 = sv.x; s1 = sv.y; s2 = sv.z; s3 = sv.w;
        d0 = dv.x; d1 = dv.y; d2 = dv.z; d3 = dv.w;
    }
    int sl0 = atomicAdd(&g_fillpos[d0], 1);
    int sl1 = atomicAdd(&g_fillpos[d1], 1);
    int sl2 = atomicAdd(&g_fillpos[d2], 1);
    int sl3 = atomicAdd(&g_fillpos[d3], 1);
    g_csr[sl0] = s0;
    g_csr[sl1] = s1;
    g_csr[sl2] = s2;
    g_csr[sl3] = s3;
}

// Layer-1 aggregation: 4 nodes per warp, one node per 8-lane group.
// Lane layout: g = lane>>3 selects the node, q = lane&7 selects a float4
// feature quad. Each lane owns its quad accumulator -> no feature reduce.
// Per 8-edge chunk each lane loads one csr index; 8 unrolled shfl+LDG.128
// give 32 independent loads in flight per warp. Out-of-range slots read the
// node's own row with weight 0 (branch-free).
__global__ __launch_bounds__(512) void k_agg1(const float* __restrict__ b1,
                                              const float* __restrict__ W2) {
    int warp = (blockIdx.x * 512 + threadIdx.x) >> 5;
    int lane = threadIdx.x & 31;
    int g = lane >> 3;          // node sub-slot 0..3
    int q = lane & 7;           // feature quad 0..7
    int node = warp * 4 + g;
    if (node >= N_NODES) return;   // N_NODES % 4 == 0 -> whole warps only

    int off = g_off[node];
    int len = g_deg[node];
    float di = __ldg(&g_dinv[node]);
    const float4* hbase = (const float4*)g_h;

    // warp-max of the 4 group degrees keeps the loop uniform (shfl-safe)
    int maxlen = len;
    maxlen = max(maxlen, __shfl_xor_sync(0xffffffffu, maxlen, 8));
    maxlen = max(maxlen, __shfl_xor_sync(0xffffffffu, maxlen, 16));

    float4 acc = make_float4(0.f, 0.f, 0.f, 0.f);
    for (int base = 0; base < maxlen; base += 8) {
        int k = base + q;
        int sl = (k < len) ? __ldg(&g_csr[off + k]) : node;
#pragma unroll
        for (int j = 0; j < 8; j++) {
            int s = __shfl_sync(0xffffffffu, sl, g * 8 + j);
            float wgt = (base + j < len) ? 1.f : 0.f;
            float4 hv = __ldg(hbase + s * (NH / 4) + q);
            acc.x += hv.x * wgt;
            acc.y += hv.y * wgt;
            acc.z += hv.z * wgt;
            acc.w += hv.w * wgt;
        }
    }

    // epilogue (all lanes active): lane owns features q*4 .. q*4+3 of node g
    float4 hv = *(hbase + node * (NH / 4) + q);     // self loop
    float4 bv = __ldg((const float4*)b1 + q);
    unsigned mask = __ldg(&g_mask[node]) >> (q * 4);
    float e0 = fmaxf((acc.x + hv.x) * di + bv.x, 0.f);
    float e1 = fmaxf((acc.y + hv.y) * di + bv.y, 0.f);
    float e2 = fmaxf((acc.z + hv.z) * di + bv.z, 0.f);
    float e3 = fmaxf((acc.w + hv.w) * di + bv.w, 0.f);
    e0 = (mask & 1u) ? e0 * 1.25f : 0.f;
    e1 = (mask & 2u) ? e1 * 1.25f : 0.f;
    e2 = (mask & 4u) ? e2 * 1.25f : 0.f;
    e3 = (mask & 8u) ? e3 * 1.25f : 0.f;
    // W2 rows c*2 {+0,+1}: two float4 = rows q*4..q*4+3
    float4 wa = __ldg((const float4*)W2 + q * 2);
    float4 wb = __ldg((const float4*)W2 + q * 2 + 1);
    float p0 = e0 * wa.x + e1 * wa.z + e2 * wb.x + e3 * wb.z;
    float p1 = e0 * wa.y + e1 * wa.w + e2 * wb.y + e3 * wb.w;
    // reduce within the 8-lane group (xor offsets stay inside the group)
#pragma unroll
    for (int o = 4; o; o >>= 1) {
        p0 += __shfl_xor_sync(0xffffffffu, p0, o);
        p1 += __shfl_xor_sync(0xffffffffu, p1, o);
    }
    if (q == 0) {
        g_g[node * 2 + 0] = p0 * di;
        g_g[node * 2 + 1] = p1 * di;
    }
}

// Layer-2 aggregation (gather, warp per node) fused with b2 + log_softmax.
// Tail: reset g_deg / g_cursor to zero for the next graph replay.
__global__ __launch_bounds__(512) void k_agg2(const float* __restrict__ b2,
                                              float* __restrict__ out) {
    int node = (blockIdx.x * 512 + threadIdx.x) >> 5;
    int lane = threadIdx.x & 31;
    if (node >= N_NODES) return;

    int off = g_off[node];
    int len = g_deg[node];
    float di = __ldg(&g_dinv[node]);
    float a0 = 0.f, a1 = 0.f;
    for (int k = lane; k < len; k += 32) {
        int s = __ldg(&g_csr[off + k]);
        float2 gv = *(const float2*)(g_g + (size_t)s * 2);
        a0 += gv.x;
        a1 += gv.y;
    }
#pragma unroll
    for (int o = 16; o; o >>= 1) {
        a0 += __shfl_xor_sync(0xffffffffu, a0, o);
        a1 += __shfl_xor_sync(0xffffffffu, a1, o);
    }
    if (lane == 0) {
        float la = (a0 + g_g[node * 2 + 0]) * di + __ldg(&b2[0]);
        float lb = (a1 + g_g[node * 2 + 1]) * di + __ldg(&b2[1]);
        float m = fmaxf(la, lb);
        float lse = m + logf(expf(la - m) + expf(lb - m));
        *(float2*)(out + (size_t)node * 2) = make_float2(la - lse, lb - lse);
        g_deg[node] = 0;                       // reset for next replay
        if (node == 0) g_cursor = 0;
    }
}

// ---------------- launch ----------------
extern "C" void kernel_launch(void* const* d_in, const int* in_sizes, int n_in,
                              void* d_out, int out_size) {
    const float* x  = (const float*)d_in[0];
    const void*  ei = d_in[1];
    const float* W1 = (const float*)d_in[2];
    const float* b1 = (const float*)d_in[3];
    const float* W2 = (const float*)d_in[4];
    const float* b2 = (const float*)d_in[5];
    float* out = (float*)d_out;

    int edge4_blocks = (N_EDGES / 4 + 255) / 256;
    k_deg<<<edge4_blocks, 256>>>((const unsigned*)ei);
    k_gemm1<<<(N_NODES + 255) / 256, 256>>>(x, W1);
    k_fill<<<edge4_blocks, 256>>>((const unsigned*)ei);
    k_agg1<<<(N_NODES / 4 + 15) / 16, 512>>>(b1, W2);
    k_agg2<<<(int)(((long long)N_NODES * 32 + 511) / 512), 512>>>(b2, out);
}

// round 13
// speedup vs baseline: 1.0820x; 1.0820x over previous
#include <cuda_runtime.h>
#include <cstdint>

#define N_NODES 100000
#define N_EDGES 1600000
#define NF 100
#define NH 32
#define GEMM_BLOCKS ((N_NODES + 255) / 256)   // 391

typedef unsigned long long u64;

// ---------------- device scratch (no allocations allowed) ----------------
// g_deg, g_cursor, g_bar are zero at module load; k_agg2 re-zeroes them at the
// end of every call so each graph replay starts from the same state.
__device__ int      g_cursor;
__device__ int      g_bar;
__device__ int      g_deg    [N_NODES];
__device__ int      g_off    [N_NODES];
__device__ int      g_fillpos[N_NODES];
__device__ float    g_dinv   [N_NODES];
__device__ unsigned g_mask   [N_NODES];    // 32-bit dropout keep-mask per node
__device__ int      g_csr    [N_EDGES];    // src per CSR slot (grouped by dst)
__device__ float    g_h      [N_NODES * NH];  // h' = (x @ W1) * dinv[row]
__device__ float    g_g      [N_NODES * 2];   // g' = (dropout(relu(.+b1)) @ W2) * dinv[row]

// ---------------- helpers ----------------
// Block-local int64-vs-int32 detection: for int64 ids < 2^31 every odd 32-bit
// word of the src half is zero; for int32 those words are random node ids.
__device__ __forceinline__ int detect_is64(const unsigned* ei) {
    int any = (threadIdx.x < 256 && ei[2 * threadIdx.x + 1] != 0u) ? 1 : 0;
    return __syncthreads_or(any) ? 0 : 1;
}

// JAX threefry2x32, key = (0, 42)  [jax.random.key(42)], 20 rounds
__device__ __forceinline__ uint2 threefry_0_42(unsigned x0, unsigned x1) {
    const unsigned ks0 = 0u, ks1 = 42u, ks2 = 0x1BD11BDAu ^ 42u;
    x0 += ks0; x1 += ks1;
#define TFR(r) { x0 += x1; x1 = ((x1 << (r)) | (x1 >> (32 - (r)))) ^ x0; }
    TFR(13) TFR(15) TFR(26) TFR(6)
    x0 += ks1; x1 += ks2 + 1u;
    TFR(17) TFR(29) TFR(16) TFR(24)
    x0 += ks2; x1 += ks0 + 2u;
    TFR(13) TFR(15) TFR(26) TFR(6)
    x0 += ks0; x1 += ks1 + 3u;
    TFR(17) TFR(29) TFR(16) TFR(24)
    x0 += ks1; x1 += ks2 + 4u;
    TFR(13) TFR(15) TFR(26) TFR(6)
    x0 += ks2; x1 += ks0 + 5u;
#undef TFR
    return make_uint2(x0, x1);
}

// Partitionable threefry: counter (0, idx), bits = out0 ^ out1.
// keep iff (bits >> 9) < 6710887  (u < 0.8f)
__device__ __forceinline__ int keep_bit(unsigned idx) {
    uint2 o = threefry_0_42(0u, idx);
    return (((o.x ^ o.y) >> 9) < 6710887u) ? 1 : 0;
}

// ---------------- kernels ----------------

// Fused: [phase A] per-thread edge-degree counting -> arrive on g_bar;
// [body] h = x @ W1 (hides the barrier); [wait] spin g_bar; [phase B]
// per-block scan of deg -> CSR offsets, dinv, fillpos; epilogue h' = h*dinv.
// Grid MUST be a single wave (391 blocks, ~34KB smem) -> spin-wait is safe.
__global__ __launch_bounds__(256) void k_fused(const float* __restrict__ x,
                                               const float* __restrict__ W1,
                                               const unsigned* __restrict__ ei) {
    __shared__ float Ws[NF * NH];      // 100x32
    __shared__ float xs[20 * 264];     // k-chunk of x, transposed, padded
    __shared__ int   s_scan[256];
    __shared__ int   s_base;
    const int tid  = threadIdx.x;
    const int row0 = blockIdx.x * 256;
    const int rg = tid >> 2;           // 0..63 -> rows rg*4..rg*4+3
    const int cg = tid & 3;            // 0..3  -> cols cg*8..cg*8+7

    // ---- phase A: degree counting (up to 16 edges per thread, vectorized) ----
    // Edge-quad partition: e0 = (t + v*TOTAL_THREADS)*4 tiles [0, N_EDGES)
    // exactly once (guarded).
    {
        int is64 = detect_is64(ei);
        int t = blockIdx.x * 256 + tid;
#pragma unroll
        for (int v = 0; v < 4; v++) {
            int e0 = (t + v * GEMM_BLOCKS * 256) * 4;
            if (e0 < N_EDGES) {
                int d0, d1, d2, d3;
                if (is64) {
                    const longlong2* p = (const longlong2*)((const long long*)ei + N_EDGES + e0);
                    longlong2 a = __ldg(p), b = __ldg(p + 1);
                    d0 = (int)a.x; d1 = (int)a.y; d2 = (int)b.x; d3 = (int)b.y;
                } else {
                    int4 dv = __ldg((const int4*)((const int*)ei + N_EDGES + e0));
                    d0 = dv.x; d1 = dv.y; d2 = dv.z; d3 = dv.w;
                }
                atomicAdd(&g_deg[d0], 1);
                atomicAdd(&g_deg[d1], 1);
                atomicAdd(&g_deg[d2], 1);
                atomicAdd(&g_deg[d3], 1);
            }
        }
        __threadfence();
        __syncthreads();
        if (tid == 0) atomicAdd(&g_bar, 1);
    }

    // ---- GEMM body (independent of deg; hides the barrier) ----
    for (int i = tid; i < NF * NH; i += 256) Ws[i] = W1[i];

    u64 acc[4][4];
#pragma unroll
    for (int i = 0; i < 4; i++)
#pragma unroll
        for (int j = 0; j < 4; j++) acc[i][j] = 0ull;

    for (int kc = 0; kc < 5; kc++) {
        __syncthreads();
        {
            int gr = row0 + tid;
            if (gr >= N_NODES) gr = N_NODES - 1;
            const float4* xp = (const float4*)(x + (size_t)gr * NF + kc * 20);
#pragma unroll
            for (int q = 0; q < 5; q++) {
                float4 v = __ldg(xp + q);
                xs[(q * 4 + 0) * 264 + tid] = v.x;
                xs[(q * 4 + 1) * 264 + tid] = v.y;
                xs[(q * 4 + 2) * 264 + tid] = v.z;
                xs[(q * 4 + 3) * 264 + tid] = v.w;
            }
        }
        __syncthreads();
#pragma unroll
        for (int kk = 0; kk < 20; kk++) {
            float4 xv = *(const float4*)&xs[kk * 264 + rg * 4];
            const u64* wp = (const u64*)&Ws[(kc * 20 + kk) * NH + cg * 8];
            u64 w0 = wp[0], w1 = wp[1], w2 = wp[2], w3 = wp[3];
            u64 xd0, xd1, xd2, xd3;
            asm("mov.b64 %0,{%1,%1};" : "=l"(xd0) : "r"(__float_as_uint(xv.x)));
            asm("mov.b64 %0,{%1,%1};" : "=l"(xd1) : "r"(__float_as_uint(xv.y)));
            asm("mov.b64 %0,{%1,%1};" : "=l"(xd2) : "r"(__float_as_uint(xv.z)));
            asm("mov.b64 %0,{%1,%1};" : "=l"(xd3) : "r"(__float_as_uint(xv.w)));
#define FMA2(a, b, c) asm("fma.rn.f32x2 %0,%1,%2,%0;" : "+l"(a) : "l"(b), "l"(c))
            FMA2(acc[0][0], xd0, w0); FMA2(acc[0][1], xd0, w1);
            FMA2(acc[0][2], xd0, w2); FMA2(acc[0][3], xd0, w3);
            FMA2(acc[1][0], xd1, w0); FMA2(acc[1][1], xd1, w1);
            FMA2(acc[1][2], xd1, w2); FMA2(acc[1][3], xd1, w3);
            FMA2(acc[2][0], xd2, w0); FMA2(acc[2][1], xd2, w1);
            FMA2(acc[2][2], xd2, w2); FMA2(acc[2][3], xd2, w3);
            FMA2(acc[3][0], xd3, w0); FMA2(acc[3][1], xd3, w1);
            FMA2(acc[3][2], xd3, w2); FMA2(acc[3][3], xd3, w3);
#undef FMA2
        }
    }

    // ---- wait for all blocks' phase A ----
    if (tid == 0) {
        while (atomicAdd(&g_bar, 0) < GEMM_BLOCKS) { }
    }
    __syncthreads();
    __threadfence();

    // ---- phase B: offsets + dinv + fillpos ----
    {
        int gr = row0 + tid;
        int mydeg = (gr < N_NODES) ? g_deg[gr] : 0;
        if (gr < N_NODES) g_dinv[gr] = rsqrtf((float)(mydeg + 1));
        s_scan[tid] = mydeg;
        __syncthreads();
#pragma unroll
        for (int off = 1; off < 256; off <<= 1) {
            int v = (tid >= off) ? s_scan[tid - off] : 0;
            __syncthreads();
            s_scan[tid] += v;
            __syncthreads();
        }
        if (tid == 255) s_base = atomicAdd(&g_cursor, s_scan[255]);
        __syncthreads();
        if (gr < N_NODES) {
            int my_off = s_base + s_scan[tid] - mydeg;
            g_off[gr] = my_off;
            g_fillpos[gr] = my_off;
        }
    }

    // h' = h * dinv[row]  (dinv for in-block rows written in phase B)
    __syncthreads();
#pragma unroll
    for (int ri = 0; ri < 4; ri++) {
        int gr = row0 + rg * 4 + ri;
        if (gr < N_NODES) {
            float di = g_dinv[gr];
            float2 p0 = *(float2*)&acc[ri][0];
            float2 p1 = *(float2*)&acc[ri][1];
            float2 p2 = *(float2*)&acc[ri][2];
            float2 p3 = *(float2*)&acc[ri][3];
            float* hp = g_h + (size_t)gr * NH + cg * 8;
            *(float4*)(hp)     = make_float4(p0.x * di, p0.y * di, p1.x * di, p1.y * di);
            *(float4*)(hp + 4) = make_float4(p2.x * di, p2.y * di, p3.x * di, p3.y * di);
        }
    }
}

// Scatter src into CSR slots (4 edges/thread, atomic cursor per dst) AND
// compute dropout masks: each warp covers 8 nodes via 8 ballot rounds (threefry
// ALU hides under the memory stalls). Grid = N_EDGES/4 threads.
__global__ __launch_bounds__(256) void k_fill(const unsigned* ei) {
    int is64 = detect_is64(ei);
    int t = blockIdx.x * 256 + threadIdx.x;
    int lane = threadIdx.x & 31;

    // dropout masks: warp w -> nodes 8w .. 8w+7
    int w = t >> 5;
    int nbase = w * 8;
    unsigned mymask = 0;
#pragma unroll
    for (int j = 0; j < 8; j++) {
        int n = nbase + j;
        unsigned m = __ballot_sync(0xffffffffu,
                                   (n < N_NODES) && keep_bit((unsigned)(n * 32 + lane)));
        if (lane == j) mymask = m;
    }
    if (lane < 8 && nbase + lane < N_NODES) g_mask[nbase + lane] = mymask;

    // CSR fill: 4 edges per thread
    int e0 = t * 4;
    if (e0 >= N_EDGES) return;
    int s0, s1, s2, s3, d0, d1, d2, d3;
    if (is64) {
        const longlong2* ps = (const longlong2*)((const long long*)ei + e0);
        const longlong2* pd = (const longlong2*)((const long long*)ei + N_EDGES + e0);
        longlong2 sa = __ldg(ps), sb = __ldg(ps + 1);
        longlong2 da = __ldg(pd), db = __ldg(pd + 1);
        s0 = (int)sa.x; s1 = (int)sa.y; s2 = (int)sb.x; s3 = (int)sb.y;
        d0 = (int)da.x; d1 = (int)da.y; d2 = (int)db.x; d3 = (int)db.y;
    } else {
        int4 sv = __ldg((const int4*)((const int*)ei + e0));
        int4 dv = __ldg((const int4*)((const int*)ei + N_EDGES + e0));
        s0 = sv.x; s1 = sv.y; s2 = sv.z; s3 = sv.w;
        d0 = dv.x; d1 = dv.y; d2 = dv.z; d3 = dv.w;
    }
    int sl0 = atomicAdd(&g_fillpos[d0], 1);
    int sl1 = atomicAdd(&g_fillpos[d1], 1);
    int sl2 = atomicAdd(&g_fillpos[d2], 1);
    int sl3 = atomicAdd(&g_fillpos[d3], 1);
    g_csr[sl0] = s0;
    g_csr[sl1] = s1;
    g_csr[sl2] = s2;
    g_csr[sl3] = s3;
}

// Layer-1 aggregation: 4 nodes per warp, one node per 8-lane group.
// Lane layout: g = lane>>3 selects the node, q = lane&7 selects a float4
// feature quad. Each lane owns its quad accumulator -> no feature reduce.
__global__ __launch_bounds__(512) void k_agg1(const float* __restrict__ b1,
                                              const float* __restrict__ W2) {
    int warp = (blockIdx.x * 512 + threadIdx.x) >> 5;
    int lane = threadIdx.x & 31;
    int g = lane >> 3;          // node sub-slot 0..3
    int q = lane & 7;           // feature quad 0..7
    int node = warp * 4 + g;
    if (node >= N_NODES) return;   // N_NODES % 4 == 0 -> whole warps only

    int off = g_off[node];
    int len = g_deg[node];
    float di = __ldg(&g_dinv[node]);
    const float4* hbase = (const float4*)g_h;

    // warp-max of the 4 group degrees keeps the loop uniform (shfl-safe)
    int maxlen = len;
    maxlen = max(maxlen, __shfl_xor_sync(0xffffffffu, maxlen, 8));
    maxlen = max(maxlen, __shfl_xor_sync(0xffffffffu, maxlen, 16));

    float4 acc = make_float4(0.f, 0.f, 0.f, 0.f);
    for (int base = 0; base < maxlen; base += 8) {
        int k = base + q;
        int sl = (k < len) ? __ldg(&g_csr[off + k]) : node;
#pragma unroll
        for (int j = 0; j < 8; j++) {
            int s = __shfl_sync(0xffffffffu, sl, g * 8 + j);
            float wgt = (base + j < len) ? 1.f : 0.f;
            float4 hv = __ldg(hbase + s * (NH / 4) + q);
            acc.x += hv.x * wgt;
            acc.y += hv.y * wgt;
            acc.z += hv.z * wgt;
            acc.w += hv.w * wgt;
        }
    }

    // epilogue (all lanes active): lane owns features q*4 .. q*4+3 of node g
    float4 hv = *(hbase + node * (NH / 4) + q);     // self loop
    float4 bv = __ldg((const float4*)b1 + q);
    unsigned mask = __ldg(&g_mask[node]) >> (q * 4);
    float e0 = fmaxf((acc.x + hv.x) * di + bv.x, 0.f);
    float e1 = fmaxf((acc.y + hv.y) * di + bv.y, 0.f);
    float e2 = fmaxf((acc.z + hv.z) * di + bv.z, 0.f);
    float e3 = fmaxf((acc.w + hv.w) * di + bv.w, 0.f);
    e0 = (mask & 1u) ? e0 * 1.25f : 0.f;
    e1 = (mask & 2u) ? e1 * 1.25f : 0.f;
    e2 = (mask & 4u) ? e2 * 1.25f : 0.f;
    e3 = (mask & 8u) ? e3 * 1.25f : 0.f;
    // W2 rows c*2 {+0,+1}: two float4 = rows q*4..q*4+3
    float4 wa = __ldg((const float4*)W2 + q * 2);
    float4 wb = __ldg((const float4*)W2 + q * 2 + 1);
    float p0 = e0 * wa.x + e1 * wa.z + e2 * wb.x + e3 * wb.z;
    float p1 = e0 * wa.y + e1 * wa.w + e2 * wb.y + e3 * wb.w;
    // reduce within the 8-lane group (xor offsets stay inside the group)
#pragma unroll
    for (int o = 4; o; o >>= 1) {
        p0 += __shfl_xor_sync(0xffffffffu, p0, o);
        p1 += __shfl_xor_sync(0xffffffffu, p1, o);
    }
    if (q == 0) {
        g_g[node * 2 + 0] = p0 * di;
        g_g[node * 2 + 1] = p1 * di;
    }
}

// Layer-2 aggregation: 4 nodes per warp, 8-lane groups; each lane gathers its
// own 8B g_g entry (no broadcast needed). Fused with b2 + log_softmax.
// Tail: reset g_deg / g_cursor / g_bar for the next graph replay.
__global__ __launch_bounds__(512) void k_agg2(const float* __restrict__ b2,
                                              float* __restrict__ out) {
    int warp = (blockIdx.x * 512 + threadIdx.x) >> 5;
    int lane = threadIdx.x & 31;
    int g = lane >> 3;
    int q = lane & 7;
    int node = warp * 4 + g;
    if (node >= N_NODES) return;

    int off = g_off[node];
    int len = g_deg[node];
    float di = __ldg(&g_dinv[node]);

    int maxlen = len;
    maxlen = max(maxlen, __shfl_xor_sync(0xffffffffu, maxlen, 8));
    maxlen = max(maxlen, __shfl_xor_sync(0xffffffffu, maxlen, 16));

    float a0 = 0.f, a1 = 0.f;
    for (int base = 0; base < maxlen; base += 8) {
        int k = base + q;
        int s = (k < len) ? __ldg(&g_csr[off + k]) : node;
        float wgt = (k < len) ? 1.f : 0.f;
        float2 gv = *(const float2*)(g_g + (size_t)s * 2);
        a0 += gv.x * wgt;
        a1 += gv.y * wgt;
    }
#pragma unroll
    for (int o = 4; o; o >>= 1) {
        a0 += __shfl_xor_sync(0xffffffffu, a0, o);
        a1 += __shfl_xor_sync(0xffffffffu, a1, o);
    }
    if (q == 0) {
        float la = (a0 + g_g[node * 2 + 0]) * di + __ldg(&b2[0]);
        float lb = (a1 + g_g[node * 2 + 1]) * di + __ldg(&b2[1]);
        float m = fmaxf(la, lb);
        float lse = m + logf(expf(la - m) + expf(lb - m));
        *(float2*)(out + (size_t)node * 2) = make_float2(la - lse, lb - lse);
        g_deg[node] = 0;                       // reset for next replay
        if (node == 0) { g_cursor = 0; g_bar = 0; }
    }
}

// ---------------- launch ----------------
extern "C" void kernel_launch(void* const* d_in, const int* in_sizes, int n_in,
                              void* d_out, int out_size) {
    const float* x  = (const float*)d_in[0];
    const void*  ei = d_in[1];
    const float* W1 = (const float*)d_in[2];
    const float* b1 = (const float*)d_in[3];
    const float* W2 = (const float*)d_in[4];
    const float* b2 = (const float*)d_in[5];
    float* out = (float*)d_out;

    k_fused<<<GEMM_BLOCKS, 256>>>(x, W1, (const unsigned*)ei);
    k_fill<<<(N_EDGES / 4 + 255) / 256, 256>>>((const unsigned*)ei);
    k_agg1<<<(N_NODES / 4 + 15) / 16, 512>>>(b1, W2);
    k_agg2<<<(N_NODES / 4 + 15) / 16, 512>>>(b2, out);
}

// round 14
// speedup vs baseline: 1.0908x; 1.0082x over previous
#include <cuda_runtime.h>
#include <cstdint>

#define N_NODES 100000
#define N_EDGES 1600000
#define NF 100
#define NH 32
#define GEMM_BLOCKS ((N_NODES + 255) / 256)   // 391

typedef unsigned long long u64;

// ---------------- device scratch (no allocations allowed) ----------------
// g_deg, g_cursor, g_bar are zero at module load; k_agg2 re-zeroes them at the
// end of every call so each graph replay starts from the same state.
__device__ int      g_cursor;
__device__ int      g_bar;
__device__ int      g_deg    [N_NODES];
__device__ int      g_off    [N_NODES];
__device__ int      g_fillpos[N_NODES];
__device__ float    g_dinv   [N_NODES];
__device__ unsigned g_mask   [N_NODES];    // 32-bit dropout keep-mask per node
__device__ int      g_csr    [N_EDGES];    // src per CSR slot (grouped by dst)
__device__ float    g_h      [N_NODES * NH];  // h' = (x @ W1) * dinv[row]
__device__ float    g_g      [N_NODES * 2];   // g' = (dropout(relu(.+b1)) @ W2) * dinv[row]

// ---------------- helpers ----------------
// Block-local int64-vs-int32 detection: for int64 ids < 2^31 every odd 32-bit
// word of the src half is zero; for int32 those words are random node ids.
__device__ __forceinline__ int detect_is64(const unsigned* ei) {
    int any = (threadIdx.x < 256 && ei[2 * threadIdx.x + 1] != 0u) ? 1 : 0;
    return __syncthreads_or(any) ? 0 : 1;
}

// JAX threefry2x32, key = (0, 42)  [jax.random.key(42)], 20 rounds
__device__ __forceinline__ uint2 threefry_0_42(unsigned x0, unsigned x1) {
    const unsigned ks0 = 0u, ks1 = 42u, ks2 = 0x1BD11BDAu ^ 42u;
    x0 += ks0; x1 += ks1;
#define TFR(r) { x0 += x1; x1 = ((x1 << (r)) | (x1 >> (32 - (r)))) ^ x0; }
    TFR(13) TFR(15) TFR(26) TFR(6)
    x0 += ks1; x1 += ks2 + 1u;
    TFR(17) TFR(29) TFR(16) TFR(24)
    x0 += ks2; x1 += ks0 + 2u;
    TFR(13) TFR(15) TFR(26) TFR(6)
    x0 += ks0; x1 += ks1 + 3u;
    TFR(17) TFR(29) TFR(16) TFR(24)
    x0 += ks1; x1 += ks2 + 4u;
    TFR(13) TFR(15) TFR(26) TFR(6)
    x0 += ks2; x1 += ks0 + 5u;
#undef TFR
    return make_uint2(x0, x1);
}

// Partitionable threefry: counter (0, idx), bits = out0 ^ out1.
// keep iff (bits >> 9) < 6710887  (u < 0.8f)
__device__ __forceinline__ int keep_bit(unsigned idx) {
    uint2 o = threefry_0_42(0u, idx);
    return (((o.x ^ o.y) >> 9) < 6710887u) ? 1 : 0;
}

// ---------------- kernels ----------------

// Fused: [phase A] per-thread edge-degree counting -> arrive on g_bar;
// [body] h = x @ W1 (hides the barrier); [wait] spin g_bar; [phase B]
// per-block scan of deg -> CSR offsets, dinv, fillpos; epilogue h' = h*dinv.
// Grid MUST be a single wave (391 blocks, ~34KB smem) -> spin-wait is safe.
__global__ __launch_bounds__(256) void k_fused(const float* __restrict__ x,
                                               const float* __restrict__ W1,
                                               const unsigned* __restrict__ ei) {
    __shared__ float Ws[NF * NH];      // 100x32
    __shared__ float xs[20 * 264];     // k-chunk of x, transposed, padded
    __shared__ int   s_scan[256];
    __shared__ int   s_base;
    const int tid  = threadIdx.x;
    const int row0 = blockIdx.x * 256;
    const int rg = tid >> 2;           // 0..63 -> rows rg*4..rg*4+3
    const int cg = tid & 3;            // 0..3  -> cols cg*8..cg*8+7

    // ---- phase A: degree counting (up to 16 edges per thread, vectorized) ----
    {
        int is64 = detect_is64(ei);
        int t = blockIdx.x * 256 + tid;
#pragma unroll
        for (int v = 0; v < 4; v++) {
            int e0 = (t + v * GEMM_BLOCKS * 256) * 4;
            if (e0 < N_EDGES) {
                int d0, d1, d2, d3;
                if (is64) {
                    const longlong2* p = (const longlong2*)((const long long*)ei + N_EDGES + e0);
                    longlong2 a = __ldg(p), b = __ldg(p + 1);
                    d0 = (int)a.x; d1 = (int)a.y; d2 = (int)b.x; d3 = (int)b.y;
                } else {
                    int4 dv = __ldg((const int4*)((const int*)ei + N_EDGES + e0));
                    d0 = dv.x; d1 = dv.y; d2 = dv.z; d3 = dv.w;
                }
                atomicAdd(&g_deg[d0], 1);
                atomicAdd(&g_deg[d1], 1);
                atomicAdd(&g_deg[d2], 1);
                atomicAdd(&g_deg[d3], 1);
            }
        }
        __threadfence();
        __syncthreads();
        if (tid == 0) atomicAdd(&g_bar, 1);
    }

    // ---- GEMM body (independent of deg; hides the barrier) ----
    for (int i = tid; i < NF * NH; i += 256) Ws[i] = W1[i];

    u64 acc[4][4];
#pragma unroll
    for (int i = 0; i < 4; i++)
#pragma unroll
        for (int j = 0; j < 4; j++) acc[i][j] = 0ull;

    for (int kc = 0; kc < 5; kc++) {
        __syncthreads();
        {
            int gr = row0 + tid;
            if (gr >= N_NODES) gr = N_NODES - 1;
            const float4* xp = (const float4*)(x + (size_t)gr * NF + kc * 20);
#pragma unroll
            for (int q = 0; q < 5; q++) {
                float4 v = __ldg(xp + q);
                xs[(q * 4 + 0) * 264 + tid] = v.x;
                xs[(q * 4 + 1) * 264 + tid] = v.y;
                xs[(q * 4 + 2) * 264 + tid] = v.z;
                xs[(q * 4 + 3) * 264 + tid] = v.w;
            }
        }
        __syncthreads();
#pragma unroll
        for (int kk = 0; kk < 20; kk++) {
            float4 xv = *(const float4*)&xs[kk * 264 + rg * 4];
            const u64* wp = (const u64*)&Ws[(kc * 20 + kk) * NH + cg * 8];
            u64 w0 = wp[0], w1 = wp[1], w2 = wp[2], w3 = wp[3];
            u64 xd0, xd1, xd2, xd3;
            asm("mov.b64 %0,{%1,%1};" : "=l"(xd0) : "r"(__float_as_uint(xv.x)));
            asm("mov.b64 %0,{%1,%1};" : "=l"(xd1) : "r"(__float_as_uint(xv.y)));
            asm("mov.b64 %0,{%1,%1};" : "=l"(xd2) : "r"(__float_as_uint(xv.z)));
            asm("mov.b64 %0,{%1,%1};" : "=l"(xd3) : "r"(__float_as_uint(xv.w)));
#define FMA2(a, b, c) asm("fma.rn.f32x2 %0,%1,%2,%0;" : "+l"(a) : "l"(b), "l"(c))
            FMA2(acc[0][0], xd0, w0); FMA2(acc[0][1], xd0, w1);
            FMA2(acc[0][2], xd0, w2); FMA2(acc[0][3], xd0, w3);
            FMA2(acc[1][0], xd1, w0); FMA2(acc[1][1], xd1, w1);
            FMA2(acc[1][2], xd1, w2); FMA2(acc[1][3], xd1, w3);
            FMA2(acc[2][0], xd2, w0); FMA2(acc[2][1], xd2, w1);
            FMA2(acc[2][2], xd2, w2); FMA2(acc[2][3], xd2, w3);
            FMA2(acc[3][0], xd3, w0); FMA2(acc[3][1], xd3, w1);
            FMA2(acc[3][2], xd3, w2); FMA2(acc[3][3], xd3, w3);
#undef FMA2
        }
    }

    // ---- wait for all blocks' phase A ----
    if (tid == 0) {
        while (atomicAdd(&g_bar, 0) < GEMM_BLOCKS) { }
    }
    __syncthreads();
    __threadfence();

    // ---- phase B: offsets + dinv + fillpos ----
    {
        int gr = row0 + tid;
        int mydeg = (gr < N_NODES) ? g_deg[gr] : 0;
        if (gr < N_NODES) g_dinv[gr] = rsqrtf((float)(mydeg + 1));
        s_scan[tid] = mydeg;
        __syncthreads();
#pragma unroll
        for (int off = 1; off < 256; off <<= 1) {
            int v = (tid >= off) ? s_scan[tid - off] : 0;
            __syncthreads();
            s_scan[tid] += v;
            __syncthreads();
        }
        if (tid == 255) s_base = atomicAdd(&g_cursor, s_scan[255]);
        __syncthreads();
        if (gr < N_NODES) {
            int my_off = s_base + s_scan[tid] - mydeg;
            g_off[gr] = my_off;
            g_fillpos[gr] = my_off;
        }
    }

    // h' = h * dinv[row]  (dinv for in-block rows written in phase B)
    __syncthreads();
#pragma unroll
    for (int ri = 0; ri < 4; ri++) {
        int gr = row0 + rg * 4 + ri;
        if (gr < N_NODES) {
            float di = g_dinv[gr];
            float2 p0 = *(float2*)&acc[ri][0];
            float2 p1 = *(float2*)&acc[ri][1];
            float2 p2 = *(float2*)&acc[ri][2];
            float2 p3 = *(float2*)&acc[ri][3];
            float* hp = g_h + (size_t)gr * NH + cg * 8;
            *(float4*)(hp)     = make_float4(p0.x * di, p0.y * di, p1.x * di, p1.y * di);
            *(float4*)(hp + 4) = make_float4(p2.x * di, p2.y * di, p3.x * di, p3.y * di);
        }
    }
}

// Scatter src into CSR slots (4 edges/thread, atomic cursor per dst) AND
// compute dropout masks: each warp covers 8 nodes via 8 ballot rounds (threefry
// ALU hides under the memory stalls). Grid = N_EDGES/4 threads.
__global__ __launch_bounds__(256) void k_fill(const unsigned* ei) {
    int is64 = detect_is64(ei);
    int t = blockIdx.x * 256 + threadIdx.x;
    int lane = threadIdx.x & 31;

    // dropout masks: warp w -> nodes 8w .. 8w+7
    int w = t >> 5;
    int nbase = w * 8;
    unsigned mymask = 0;
#pragma unroll
    for (int j = 0; j < 8; j++) {
        int n = nbase + j;
        unsigned m = __ballot_sync(0xffffffffu,
                                   (n < N_NODES) && keep_bit((unsigned)(n * 32 + lane)));
        if (lane == j) mymask = m;
    }
    if (lane < 8 && nbase + lane < N_NODES) g_mask[nbase + lane] = mymask;

    // CSR fill: 4 edges per thread
    int e0 = t * 4;
    if (e0 >= N_EDGES) return;
    int s0, s1, s2, s3, d0, d1, d2, d3;
    if (is64) {
        const longlong2* ps = (const longlong2*)((const long long*)ei + e0);
        const longlong2* pd = (const longlong2*)((const long long*)ei + N_EDGES + e0);
        longlong2 sa = __ldg(ps), sb = __ldg(ps + 1);
        longlong2 da = __ldg(pd), db = __ldg(pd + 1);
        s0 = (int)sa.x; s1 = (int)sa.y; s2 = (int)sb.x; s3 = (int)sb.y;
        d0 = (int)da.x; d1 = (int)da.y; d2 = (int)db.x; d3 = (int)db.y;
    } else {
        int4 sv = __ldg((const int4*)((const int*)ei + e0));
        int4 dv = __ldg((const int4*)((const int*)ei + N_EDGES + e0));
        s0 = sv.x; s1 = sv.y; s2 = sv.z; s3 = sv.w;
        d0 = dv.x; d1 = dv.y; d2 = dv.z; d3 = dv.w;
    }
    int sl0 = atomicAdd(&g_fillpos[d0], 1);
    int sl1 = atomicAdd(&g_fillpos[d1], 1);
    int sl2 = atomicAdd(&g_fillpos[d2], 1);
    int sl3 = atomicAdd(&g_fillpos[d3], 1);
    g_csr[sl0] = s0;
    g_csr[sl1] = s1;
    g_csr[sl2] = s2;
    g_csr[sl3] = s3;
}

// Layer-1 aggregation: 4 nodes per warp, one node per 8-lane group.
// Lane layout: g = lane>>3 selects the node, q = lane&7 selects a float4
// feature quad. Each lane owns its quad accumulator -> no feature reduce.
// CSR index stream is software-pipelined: next chunk's indices load while the
// current chunk's 8 gathers are in flight.
__global__ __launch_bounds__(512, 3) void k_agg1(const float* __restrict__ b1,
                                                 const float* __restrict__ W2) {
    int warp = (blockIdx.x * 512 + threadIdx.x) >> 5;
    int lane = threadIdx.x & 31;
    int g = lane >> 3;          // node sub-slot 0..3
    int q = lane & 7;           // feature quad 0..7
    int node = warp * 4 + g;
    if (node >= N_NODES) return;   // N_NODES % 4 == 0 -> whole warps only

    int off = g_off[node];
    int len = g_deg[node];
    float di = __ldg(&g_dinv[node]);
    const float4* hbase = (const float4*)g_h;

    // warp-max of the 4 group degrees keeps the loop uniform (shfl-safe)
    int maxlen = len;
    maxlen = max(maxlen, __shfl_xor_sync(0xffffffffu, maxlen, 8));
    maxlen = max(maxlen, __shfl_xor_sync(0xffffffffu, maxlen, 16));

    float4 acc = make_float4(0.f, 0.f, 0.f, 0.f);
    int sl = (q < len) ? __ldg(&g_csr[off + q]) : node;   // prefetched chunk 0
    for (int base = 0; base < maxlen; base += 8) {
        int nk = base + 8 + q;
        int sl_next = (nk < len && base + 8 < maxlen) ? __ldg(&g_csr[off + nk]) : node;
#pragma unroll
        for (int j = 0; j < 8; j++) {
            int s = __shfl_sync(0xffffffffu, sl, g * 8 + j);
            float wgt = (base + j < len) ? 1.f : 0.f;
            float4 hv = __ldg(hbase + s * (NH / 4) + q);
            acc.x += hv.x * wgt;
            acc.y += hv.y * wgt;
            acc.z += hv.z * wgt;
            acc.w += hv.w * wgt;
        }
        sl = sl_next;
    }

    // epilogue (all lanes active): lane owns features q*4 .. q*4+3 of node g
    float4 hv = *(hbase + node * (NH / 4) + q);     // self loop
    float4 bv = __ldg((const float4*)b1 + q);
    unsigned mask = __ldg(&g_mask[node]) >> (q * 4);
    float e0 = fmaxf((acc.x + hv.x) * di + bv.x, 0.f);
    float e1 = fmaxf((acc.y + hv.y) * di + bv.y, 0.f);
    float e2 = fmaxf((acc.z + hv.z) * di + bv.z, 0.f);
    float e3 = fmaxf((acc.w + hv.w) * di + bv.w, 0.f);
    e0 = (mask & 1u) ? e0 * 1.25f : 0.f;
    e1 = (mask & 2u) ? e1 * 1.25f : 0.f;
    e2 = (mask & 4u) ? e2 * 1.25f : 0.f;
    e3 = (mask & 8u) ? e3 * 1.25f : 0.f;
    // W2 rows c*2 {+0,+1}: two float4 = rows q*4..q*4+3
    float4 wa = __ldg((const float4*)W2 + q * 2);
    float4 wb = __ldg((const float4*)W2 + q * 2 + 1);
    float p0 = e0 * wa.x + e1 * wa.z + e2 * wb.x + e3 * wb.z;
    float p1 = e0 * wa.y + e1 * wa.w + e2 * wb.y + e3 * wb.w;
    // reduce within the 8-lane group (xor offsets stay inside the group)
#pragma unroll
    for (int o = 4; o; o >>= 1) {
        p0 += __shfl_xor_sync(0xffffffffu, p0, o);
        p1 += __shfl_xor_sync(0xffffffffu, p1, o);
    }
    if (q == 0) {
        g_g[node * 2 + 0] = p0 * di;
        g_g[node * 2 + 1] = p1 * di;
    }
}

// Layer-2 aggregation: 4 nodes per warp, 8-lane groups; each lane gathers its
// own 8B g_g entry. CSR stream software-pipelined. Fused with b2 + log_softmax.
// Tail: reset g_deg / g_cursor / g_bar for the next graph replay.
__global__ __launch_bounds__(512) void k_agg2(const float* __restrict__ b2,
                                              float* __restrict__ out) {
    int warp = (blockIdx.x * 512 + threadIdx.x) >> 5;
    int lane = threadIdx.x & 31;
    int g = lane >> 3;
    int q = lane & 7;
    int node = warp * 4 + g;
    if (node >= N_NODES) return;

    int off = g_off[node];
    int len = g_deg[node];
    float di = __ldg(&g_dinv[node]);

    int maxlen = len;
    maxlen = max(maxlen, __shfl_xor_sync(0xffffffffu, maxlen, 8));
    maxlen = max(maxlen, __shfl_xor_sync(0xffffffffu, maxlen, 16));

    float a0 = 0.f, a1 = 0.f;
    int s = (q < len) ? __ldg(&g_csr[off + q]) : node;    // prefetched chunk 0
    float w0 = (q < len) ? 1.f : 0.f;
    for (int base = 0; base < maxlen; base += 8) {
        int nk = base + 8 + q;
        int s_next = (nk < len && base + 8 < maxlen) ? __ldg(&g_csr[off + nk]) : node;
        float w_next = (nk < len) ? 1.f : 0.f;
        float2 gv = *(const float2*)(g_g + (size_t)s * 2);
        a0 += gv.x * w0;
        a1 += gv.y * w0;
        s = s_next;
        w0 = w_next;
    }
#pragma unroll
    for (int o = 4; o; o >>= 1) {
        a0 += __shfl_xor_sync(0xffffffffu, a0, o);
        a1 += __shfl_xor_sync(0xffffffffu, a1, o);
    }
    if (q == 0) {
        float la = (a0 + g_g[node * 2 + 0]) * di + __ldg(&b2[0]);
        float lb = (a1 + g_g[node * 2 + 1]) * di + __ldg(&b2[1]);
        float m = fmaxf(la, lb);
        float lse = m + logf(expf(la - m) + expf(lb - m));
        *(float2*)(out + (size_t)node * 2) = make_float2(la - lse, lb - lse);
    }
    // reset for next replay (one thread per node among lanes q==1 avoids
    // serializing with the q==0 output path)
    if (q == 1) {
        g_deg[node] = 0;
        if (node == 0) { g_cursor = 0; g_bar = 0; }
    }
}

// ---------------- launch ----------------
extern "C" void kernel_launch(void* const* d_in, const int* in_sizes, int n_in,
                              void* d_out, int out_size) {
    const float* x  = (const float*)d_in[0];
    const void*  ei = d_in[1];
    const float* W1 = (const float*)d_in[2];
    const float* b1 = (const float*)d_in[3];
    const float* W2 = (const float*)d_in[4];
    const float* b2 = (const float*)d_in[5];
    float* out = (float*)d_out;

    k_fused<<<GEMM_BLOCKS, 256>>>(x, W1, (const unsigned*)ei);
    k_fill<<<(N_EDGES / 4 + 255) / 256, 256>>>((const unsigned*)ei);
    k_agg1<<<(N_NODES / 4 + 15) / 16, 512>>>(b1, W2);
    k_agg2<<<(N_NODES / 4 + 15) / 16, 512>>>(b2, out);
}

// round 15
// speedup vs baseline: 1.1215x; 1.0281x over previous
#include <cuda_runtime.h>
#include <cstdint>

#define N_NODES 100000
#define N_EDGES 1600000
#define NF 100
#define NH 32
#define GEMM_BLOCKS ((N_NODES + 255) / 256)   // 391
#define TOT_THREADS (GEMM_BLOCKS * 256)       // 100096

typedef unsigned long long u64;

// ---------------- device scratch (no allocations allowed) ----------------
// All counters are zero at module load; k_agg2 re-zeroes them at the end of
// every call so each graph replay starts from the same state.
__device__ int      g_cursor;
__device__ int      g_bar1;
__device__ int      g_bar2;
__device__ int      g_deg    [N_NODES];
__device__ int      g_off    [N_NODES];
__device__ int      g_fillpos[N_NODES];
__device__ float    g_dinv   [N_NODES];
__device__ unsigned g_mask   [N_NODES];    // 32-bit dropout keep-mask per node
__device__ int      g_csr    [N_EDGES];    // src per CSR slot (grouped by dst)
__device__ float    g_h      [N_NODES * NH];  // h' = (x @ W1) * dinv[row]
__device__ float    g_g      [N_NODES * 2];   // g' = (dropout(relu(.+b1)) @ W2) * dinv[row]

// ---------------- helpers ----------------
// Block-local int64-vs-int32 detection: for int64 ids < 2^31 every odd 32-bit
// word of the src half is zero; for int32 those words are random node ids.
__device__ __forceinline__ int detect_is64(const unsigned* ei) {
    int any = (threadIdx.x < 256 && ei[2 * threadIdx.x + 1] != 0u) ? 1 : 0;
    return __syncthreads_or(any) ? 0 : 1;
}

// JAX threefry2x32, key = (0, 42)  [jax.random.key(42)], 20 rounds
__device__ __forceinline__ uint2 threefry_0_42(unsigned x0, unsigned x1) {
    const unsigned ks0 = 0u, ks1 = 42u, ks2 = 0x1BD11BDAu ^ 42u;
    x0 += ks0; x1 += ks1;
#define TFR(r) { x0 += x1; x1 = ((x1 << (r)) | (x1 >> (32 - (r)))) ^ x0; }
    TFR(13) TFR(15) TFR(26) TFR(6)
    x0 += ks1; x1 += ks2 + 1u;
    TFR(17) TFR(29) TFR(16) TFR(24)
    x0 += ks2; x1 += ks0 + 2u;
    TFR(13) TFR(15) TFR(26) TFR(6)
    x0 += ks0; x1 += ks1 + 3u;
    TFR(17) TFR(29) TFR(16) TFR(24)
    x0 += ks1; x1 += ks2 + 4u;
    TFR(13) TFR(15) TFR(26) TFR(6)
    x0 += ks2; x1 += ks0 + 5u;
#undef TFR
    return make_uint2(x0, x1);
}

// Partitionable threefry: counter (0, idx), bits = out0 ^ out1.
// keep iff (bits >> 9) < 6710887  (u < 0.8f)
__device__ __forceinline__ int keep_bit(unsigned idx) {
    uint2 o = threefry_0_42(0u, idx);
    return (((o.x ^ o.y) >> 9) < 6710887u) ? 1 : 0;
}

// ---------------- fused kernel ----------------
// Single-wave (391 blocks, forced 3 blocks/SM). Phases:
//   A: edge-degree atomics -> arrive bar1
//   gemm kc0,kc1 (hides A's drain)
//   wait bar1 -> B: scan -> off/dinv/fillpos -> arrive bar2
//   gemm kc2 -> wait bar2
//   fill+mask interleaved with gemm kc3,kc4 (LSU/ALU co-issue with FMA pipe)
//   epilogue: h' = h * dinv
__global__ __launch_bounds__(256, 3) void k_fused(const float* __restrict__ x,
                                                  const float* __restrict__ W1,
                                                  const unsigned* __restrict__ ei) {
    __shared__ float Ws[NF * NH];      // 100x32
    __shared__ float xs[20 * 264];     // k-chunk of x, transposed, padded
    __shared__ int   s_scan[256];
    __shared__ int   s_base;
    const int tid  = threadIdx.x;
    const int row0 = blockIdx.x * 256;
    const int rg = tid >> 2;           // 0..63 -> rows rg*4..rg*4+3
    const int cg = tid & 3;            // 0..3  -> cols cg*8..cg*8+7
    const int t  = blockIdx.x * 256 + tid;
    const int lane = tid & 31;
    const int gw = t >> 5;             // global warp id 0..3127

    const int is64 = detect_is64(ei);

    // ---- phase A: degree counting (up to 16 edges per thread, vectorized) ----
    {
#pragma unroll
        for (int v = 0; v < 4; v++) {
            int e0 = (t + v * TOT_THREADS) * 4;
            if (e0 < N_EDGES) {
                int d0, d1, d2, d3;
                if (is64) {
                    const longlong2* p = (const longlong2*)((const long long*)ei + N_EDGES + e0);
                    longlong2 a = __ldg(p), b = __ldg(p + 1);
                    d0 = (int)a.x; d1 = (int)a.y; d2 = (int)b.x; d3 = (int)b.y;
                } else {
                    int4 dv = __ldg((const int4*)((const int*)ei + N_EDGES + e0));
                    d0 = dv.x; d1 = dv.y; d2 = dv.z; d3 = dv.w;
                }
                atomicAdd(&g_deg[d0], 1);
                atomicAdd(&g_deg[d1], 1);
                atomicAdd(&g_deg[d2], 1);
                atomicAdd(&g_deg[d3], 1);
            }
        }
        __threadfence();
        __syncthreads();
        if (tid == 0) atomicAdd(&g_bar1, 1);
    }

    // ---- GEMM setup ----
    for (int i = tid; i < NF * NH; i += 256) Ws[i] = W1[i];

    u64 acc[4][4];
#pragma unroll
    for (int i = 0; i < 4; i++)
#pragma unroll
        for (int j = 0; j < 4; j++) acc[i][j] = 0ull;

    auto gemm_chunk = [&](int kc) {
        __syncthreads();
        {
            int gr = row0 + tid;
            if (gr >= N_NODES) gr = N_NODES - 1;
            const float4* xp = (const float4*)(x + (size_t)gr * NF + kc * 20);
#pragma unroll
            for (int q = 0; q < 5; q++) {
                float4 v = __ldg(xp + q);
                xs[(q * 4 + 0) * 264 + tid] = v.x;
                xs[(q * 4 + 1) * 264 + tid] = v.y;
                xs[(q * 4 + 2) * 264 + tid] = v.z;
                xs[(q * 4 + 3) * 264 + tid] = v.w;
            }
        }
        __syncthreads();
#pragma unroll
        for (int kk = 0; kk < 20; kk++) {
            float4 xv = *(const float4*)&xs[kk * 264 + rg * 4];
            const u64* wp = (const u64*)&Ws[(kc * 20 + kk) * NH + cg * 8];
            u64 w0 = wp[0], w1 = wp[1], w2 = wp[2], w3 = wp[3];
            u64 xd0, xd1, xd2, xd3;
            asm("mov.b64 %0,{%1,%1};" : "=l"(xd0) : "r"(__float_as_uint(xv.x)));
            asm("mov.b64 %0,{%1,%1};" : "=l"(xd1) : "r"(__float_as_uint(xv.y)));
            asm("mov.b64 %0,{%1,%1};" : "=l"(xd2) : "r"(__float_as_uint(xv.z)));
            asm("mov.b64 %0,{%1,%1};" : "=l"(xd3) : "r"(__float_as_uint(xv.w)));
#define FMA2(a, b, c) asm("fma.rn.f32x2 %0,%1,%2,%0;" : "+l"(a) : "l"(b), "l"(c))
            FMA2(acc[0][0], xd0, w0); FMA2(acc[0][1], xd0, w1);
            FMA2(acc[0][2], xd0, w2); FMA2(acc[0][3], xd0, w3);
            FMA2(acc[1][0], xd1, w0); FMA2(acc[1][1], xd1, w1);
            FMA2(acc[1][2], xd1, w2); FMA2(acc[1][3], xd1, w3);
            FMA2(acc[2][0], xd2, w0); FMA2(acc[2][1], xd2, w1);
            FMA2(acc[2][2], xd2, w2); FMA2(acc[2][3], xd2, w3);
            FMA2(acc[3][0], xd3, w0); FMA2(acc[3][1], xd3, w1);
            FMA2(acc[3][2], xd3, w2); FMA2(acc[3][3], xd3, w3);
#undef FMA2
        }
    };

    // Fill one edge-quad (v in 0..3): vector load + 4 atomics + 4 scattered stores
    auto fill_quad = [&](int v) {
        int e0 = (t + v * TOT_THREADS) * 4;
        if (e0 < N_EDGES) {
            int s0, s1, s2, s3, d0, d1, d2, d3;
            if (is64) {
                const longlong2* ps = (const longlong2*)((const long long*)ei + e0);
                const longlong2* pd = (const longlong2*)((const long long*)ei + N_EDGES + e0);
                longlong2 sa = __ldg(ps), sb = __ldg(ps + 1);
                longlong2 da = __ldg(pd), db = __ldg(pd + 1);
                s0 = (int)sa.x; s1 = (int)sa.y; s2 = (int)sb.x; s3 = (int)sb.y;
                d0 = (int)da.x; d1 = (int)da.y; d2 = (int)db.x; d3 = (int)db.y;
            } else {
                int4 sv = __ldg((const int4*)((const int*)ei + e0));
                int4 dv = __ldg((const int4*)((const int*)ei + N_EDGES + e0));
                s0 = sv.x; s1 = sv.y; s2 = sv.z; s3 = sv.w;
                d0 = dv.x; d1 = dv.y; d2 = dv.z; d3 = dv.w;
            }
            int sl0 = atomicAdd(&g_fillpos[d0], 1);
            int sl1 = atomicAdd(&g_fillpos[d1], 1);
            int sl2 = atomicAdd(&g_fillpos[d2], 1);
            int sl3 = atomicAdd(&g_fillpos[d3], 1);
            g_csr[sl0] = s0;
            g_csr[sl1] = s1;
            g_csr[sl2] = s2;
            g_csr[sl3] = s3;
        }
    };

    // Dropout masks: warp gw owns nodes gw*32 .. gw*32+31; round r -> node
    // gw*32+r, lane r keeps the ballot result. Executed in chunks.
    unsigned mymask = 0;
    auto mask_rounds = [&](int r0, int r1) {
        for (int r = r0; r < r1; r++) {
            int n = gw * 32 + r;
            unsigned m = __ballot_sync(0xffffffffu,
                                       (n < N_NODES) && keep_bit((unsigned)(n * 32 + lane)));
            if (lane == r) mymask = m;
        }
    };

    // ---- gemm kc0,kc1 hide phase A's atomic drain ----
    gemm_chunk(0);
    gemm_chunk(1);

    // ---- wait bar1; phase B: offsets + dinv + fillpos; arrive bar2 ----
    if (tid == 0) {
        while (atomicAdd(&g_bar1, 0) < GEMM_BLOCKS) { }
    }
    __syncthreads();
    __threadfence();
    {
        int gr = row0 + tid;
        int mydeg = (gr < N_NODES) ? g_deg[gr] : 0;
        if (gr < N_NODES) g_dinv[gr] = rsqrtf((float)(mydeg + 1));
        s_scan[tid] = mydeg;
        __syncthreads();
#pragma unroll
        for (int off = 1; off < 256; off <<= 1) {
            int v = (tid >= off) ? s_scan[tid - off] : 0;
            __syncthreads();
            s_scan[tid] += v;
            __syncthreads();
        }
        if (tid == 255) s_base = atomicAdd(&g_cursor, s_scan[255]);
        __syncthreads();
        if (gr < N_NODES) {
            int my_off = s_base + s_scan[tid] - mydeg;
            g_off[gr] = my_off;
            g_fillpos[gr] = my_off;
        }
        __threadfence();
        __syncthreads();
        if (tid == 0) atomicAdd(&g_bar2, 1);
    }

    // ---- gemm kc2 while other blocks reach bar2; then wait ----
    gemm_chunk(2);
    if (tid == 0) {
        while (atomicAdd(&g_bar2, 0) < GEMM_BLOCKS) { }
    }
    __syncthreads();
    __threadfence();

    // ---- interleaved fill + mask + gemm (disjoint pipes co-issue) ----
    fill_quad(0);
    mask_rounds(0, 11);
    gemm_chunk(3);
    fill_quad(1);
    fill_quad(2);
    mask_rounds(11, 22);
    gemm_chunk(4);
    fill_quad(3);
    mask_rounds(22, 32);
    {
        int n = gw * 32 + lane;
        if (n < N_NODES) g_mask[n] = mymask;
    }

    // ---- epilogue: h' = h * dinv[row] ----
#pragma unroll
    for (int ri = 0; ri < 4; ri++) {
        int gr = row0 + rg * 4 + ri;
        if (gr < N_NODES) {
            float di = g_dinv[gr];
            float2 p0 = *(float2*)&acc[ri][0];
            float2 p1 = *(float2*)&acc[ri][1];
            float2 p2 = *(float2*)&acc[ri][2];
            float2 p3 = *(float2*)&acc[ri][3];
            float* hp = g_h + (size_t)gr * NH + cg * 8;
            *(float4*)(hp)     = make_float4(p0.x * di, p0.y * di, p1.x * di, p1.y * di);
            *(float4*)(hp + 4) = make_float4(p2.x * di, p2.y * di, p3.x * di, p3.y * di);
        }
    }
}

// Layer-1 aggregation: 4 nodes per warp, one node per 8-lane group.
// Lane layout: g = lane>>3 selects the node, q = lane&7 selects a float4
// feature quad. Each lane owns its quad accumulator -> no feature reduce.
// CSR index stream is software-pipelined.
__global__ __launch_bounds__(512, 3) void k_agg1(const float* __restrict__ b1,
                                                 const float* __restrict__ W2) {
    int warp = (blockIdx.x * 512 + threadIdx.x) >> 5;
    int lane = threadIdx.x & 31;
    int g = lane >> 3;          // node sub-slot 0..3
    int q = lane & 7;           // feature quad 0..7
    int node = warp * 4 + g;
    if (node >= N_NODES) return;   // N_NODES % 4 == 0 -> whole warps only

    int off = g_off[node];
    int len = g_deg[node];
    float di = __ldg(&g_dinv[node]);
    const float4* hbase = (const float4*)g_h;

    // warp-max of the 4 group degrees keeps the loop uniform (shfl-safe)
    int maxlen = len;
    maxlen = max(maxlen, __shfl_xor_sync(0xffffffffu, maxlen, 8));
    maxlen = max(maxlen, __shfl_xor_sync(0xffffffffu, maxlen, 16));

    float4 acc = make_float4(0.f, 0.f, 0.f, 0.f);
    int sl = (q < len) ? __ldg(&g_csr[off + q]) : node;   // prefetched chunk 0
    for (int base = 0; base < maxlen; base += 8) {
        int nk = base + 8 + q;
        int sl_next = (nk < len && base + 8 < maxlen) ? __ldg(&g_csr[off + nk]) : node;
#pragma unroll
        for (int j = 0; j < 8; j++) {
            int s = __shfl_sync(0xffffffffu, sl, g * 8 + j);
            float wgt = (base + j < len) ? 1.f : 0.f;
            float4 hv = __ldg(hbase + s * (NH / 4) + q);
            acc.x += hv.x * wgt;
            acc.y += hv.y * wgt;
            acc.z += hv.z * wgt;
            acc.w += hv.w * wgt;
        }
        sl = sl_next;
    }

    // epilogue (all lanes active): lane owns features q*4 .. q*4+3 of node g
    float4 hv = *(hbase + node * (NH / 4) + q);     // self loop
    float4 bv = __ldg((const float4*)b1 + q);
    unsigned mask = __ldg(&g_mask[node]) >> (q * 4);
    float e0 = fmaxf((acc.x + hv.x) * di + bv.x, 0.f);
    float e1 = fmaxf((acc.y + hv.y) * di + bv.y, 0.f);
    float e2 = fmaxf((acc.z + hv.z) * di + bv.z, 0.f);
    float e3 = fmaxf((acc.w + hv.w) * di + bv.w, 0.f);
    e0 = (mask & 1u) ? e0 * 1.25f : 0.f;
    e1 = (mask & 2u) ? e1 * 1.25f : 0.f;
    e2 = (mask & 4u) ? e2 * 1.25f : 0.f;
    e3 = (mask & 8u) ? e3 * 1.25f : 0.f;
    // W2 rows c*2 {+0,+1}: two float4 = rows q*4..q*4+3
    float4 wa = __ldg((const float4*)W2 + q * 2);
    float4 wb = __ldg((const float4*)W2 + q * 2 + 1);
    float p0 = e0 * wa.x + e1 * wa.z + e2 * wb.x + e3 * wb.z;
    float p1 = e0 * wa.y + e1 * wa.w + e2 * wb.y + e3 * wb.w;
    // reduce within the 8-lane group (xor offsets stay inside the group)
#pragma unroll
    for (int o = 4; o; o >>= 1) {
        p0 += __shfl_xor_sync(0xffffffffu, p0, o);
        p1 += __shfl_xor_sync(0xffffffffu, p1, o);
    }
    if (q == 0) {
        g_g[node * 2 + 0] = p0 * di;
        g_g[node * 2 + 1] = p1 * di;
    }
}

// Layer-2 aggregation: 4 nodes per warp, 8-lane groups; each lane gathers its
// own 8B g_g entry. CSR stream software-pipelined. Fused with b2 + log_softmax.
// Tail: reset counters/deg for the next graph replay.
__global__ __launch_bounds__(512) void k_agg2(const float* __restrict__ b2,
                                              float* __restrict__ out) {
    int warp = (blockIdx.x * 512 + threadIdx.x) >> 5;
    int lane = threadIdx.x & 31;
    int g = lane >> 3;
    int q = lane & 7;
    int node = warp * 4 + g;
    if (node >= N_NODES) return;

    int off = g_off[node];
    int len = g_deg[node];
    float di = __ldg(&g_dinv[node]);

    int maxlen = len;
    maxlen = max(maxlen, __shfl_xor_sync(0xffffffffu, maxlen, 8));
    maxlen = max(maxlen, __shfl_xor_sync(0xffffffffu, maxlen, 16));

    float a0 = 0.f, a1 = 0.f;
    int s = (q < len) ? __ldg(&g_csr[off + q]) : node;    // prefetched chunk 0
    float w0 = (q < len) ? 1.f : 0.f;
    for (int base = 0; base < maxlen; base += 8) {
        int nk = base + 8 + q;
        int s_next = (nk < len && base + 8 < maxlen) ? __ldg(&g_csr[off + nk]) : node;
        float w_next = (nk < len) ? 1.f : 0.f;
        float2 gv = *(const float2*)(g_g + (size_t)s * 2);
        a0 += gv.x * w0;
        a1 += gv.y * w0;
        s = s_next;
        w0 = w_next;
    }
#pragma unroll
    for (int o = 4; o; o >>= 1) {
        a0 += __shfl_xor_sync(0xffffffffu, a0, o);
        a1 += __shfl_xor_sync(0xffffffffu, a1, o);
    }
    if (q == 0) {
        float la = (a0 + g_g[node * 2 + 0]) * di + __ldg(&b2[0]);
        float lb = (a1 + g_g[node * 2 + 1]) * di + __ldg(&b2[1]);
        float m = fmaxf(la, lb);
        float lse = m + logf(expf(la - m) + expf(lb - m));
        *(float2*)(out + (size_t)node * 2) = make_float2(la - lse, lb - lse);
    }
    // reset for next replay
    if (q == 1) {
        g_deg[node] = 0;
        if (node == 0) { g_cursor = 0; g_bar1 = 0; g_bar2 = 0; }
    }
}

// ---------------- launch ----------------
extern "C" void kernel_launch(void* const* d_in, const int* in_sizes, int n_in,
                              void* d_out, int out_size) {
    const float* x  = (const float*)d_in[0];
    const void*  ei = d_in[1];
    const float* W1 = (const float*)d_in[2];
    const float* b1 = (const float*)d_in[3];
    const float* W2 = (const float*)d_in[4];
    const float* b2 = (const float*)d_in[5];
    float* out = (float*)d_out;

    k_fused<<<GEMM_BLOCKS, 256>>>(x, W1, (const unsigned*)ei);
    k_agg1<<<(N_NODES / 4 + 15) / 16, 512>>>(b1, W2);
    k_agg2<<<(N_NODES / 4 + 15) / 16, 512>>>(b2, out);
}